// round 16
// baseline (speedup 1.0000x reference)
#include <cuda_runtime.h>
#include <cuda_fp16.h>
#include <cstdint>

// ----------------------------------------------------------------------------
// Problem constants
#define B_SZ  8192
#define D_K   1024
#define U_SZ  1024
#define E_SZ  16

// GEMM tile config: 128x128 CTA tile, 8 warps (32x64 warp tiles), 2 CTAs/SM
constexpr int TM = 128;
constexpr int TN = 128;
constexpr int KC = 64;                // K per SMEM stage (fp16: 128B rows)
constexpr int NKT = D_K / KC;         // 16
constexpr int NSTAGE = 3;
constexpr int ATHREADS = 256;         // 8 warps, warp tile 32x64

// ----------------------------------------------------------------------------
// Static device scratch (allocation-free rule)
__device__ __half g_Xh[(size_t)B_SZ * D_K];                    // fp16 X
__device__ __half g_Wth[(size_t)E_SZ * U_SZ * D_K];            // fp16 W^T [e][u][d]
__device__ __half g_P[(size_t)B_SZ * E_SZ * U_SZ];             // exp(logits), b-major [b][e][u]
__device__ float  g_S[(size_t)B_SZ * E_SZ];                    // row sums Z, [b][e]

// ----------------------------------------------------------------------------
__device__ __forceinline__ uint32_t smem_u32(const void* p) {
    return (uint32_t)__cvta_generic_to_shared(p);
}
__device__ __forceinline__ void cp16(uint32_t dst, const void* src) {
    asm volatile("cp.async.cg.shared.global [%0], [%1], 16;" :: "r"(dst), "l"(src));
}
__device__ __forceinline__ void cp_commit() {
    asm volatile("cp.async.commit_group;" ::: "memory");
}
template <int N> __device__ __forceinline__ void cp_wait() {
    asm volatile("cp.async.wait_group %0;" :: "n"(N) : "memory");
}
__device__ __forceinline__ void ldsm4(uint32_t* r, uint32_t addr) {
    asm volatile("ldmatrix.sync.aligned.m8n8.x4.shared.b16 {%0,%1,%2,%3}, [%4];"
                 : "=r"(r[0]), "=r"(r[1]), "=r"(r[2]), "=r"(r[3]) : "r"(addr));
}
__device__ __forceinline__ void mma_f16(float* c, const uint32_t* a, uint32_t b0, uint32_t b1) {
    asm volatile("mma.sync.aligned.m16n8k16.row.col.f32.f16.f16.f32 "
                 "{%0,%1,%2,%3}, {%4,%5,%6,%7}, {%8,%9}, {%0,%1,%2,%3};"
                 : "+f"(c[0]), "+f"(c[1]), "+f"(c[2]), "+f"(c[3])
                 : "r"(a[0]), "r"(a[1]), "r"(a[2]), "r"(a[3]), "r"(b0), "r"(b1));
}
__device__ __forceinline__ uint32_t swz128(uint32_t off) { return off ^ ((off >> 3) & 0x70); }
__device__ __forceinline__ uint32_t pack_h2(float a, float b) {
    __half2 h = __floats2half2_rn(a, b);
    return *reinterpret_cast<uint32_t*>(&h);
}
// streaming (evict-first) global accesses for single-use data
__device__ __forceinline__ uint4 ldg_cs_v4(const void* p) {
    uint4 v;
    asm volatile("ld.global.cs.v4.u32 {%0,%1,%2,%3}, [%4];"
                 : "=r"(v.x), "=r"(v.y), "=r"(v.z), "=r"(v.w) : "l"(p));
    return v;
}
__device__ __forceinline__ void stg_cs_v4(void* p, uint4 v) {
    asm volatile("st.global.cs.v4.u32 [%0], {%1,%2,%3,%4};"
                 :: "l"(p), "r"(v.x), "r"(v.y), "r"(v.z), "r"(v.w) : "memory");
}

// ----------------------------------------------------------------------------
// SMEM layout (bytes)
constexpr int SM_BIAS  = 0;                      // 128 floats
constexpr int SM_SROW  = 512;                    // 128 floats
constexpr int SM_STAGE = 1024;                   // 1024-aligned
constexpr int A_BYTES  = TM * 128;               // 16KB
constexpr int B_BYTES  = TN * 128;               // 16KB
constexpr int STAGE_BYTES = A_BYTES + B_BYTES;   // 32KB
constexpr int SM_PACK  = SM_STAGE + NSTAGE * STAGE_BYTES;     // 99328
constexpr int PACK_STRIDE = 144;                 // 16B-aligned, 36-bank stride (conflict-free)
constexpr int PACK_BYTES  = 64 * PACK_STRIDE;    // 9216
constexpr int SMEM_TOTAL  = SM_PACK + PACK_BYTES;             // 108544 -> 2 CTAs/SM

// ----------------------------------------------------------------------------
// Kernel 1 (merged prep): convert X to fp16 (2 float4/thread), zero S,
// transpose+convert W (32u x 64d tiles, conflict-free).
constexpr int XCH   = B_SZ * D_K / 8;                                // float4s per half
constexpr int XBLK  = (B_SZ * D_K / 8) / 256;                        // 4096
constexpr int WBLK  = (U_SZ / 32) * (D_K / 64) * E_SZ;               // 8192

__global__ void prep_kernel(const float* __restrict__ X, const float* __restrict__ W) {
    if (blockIdx.x < XBLK) {
        size_t i0 = (size_t)blockIdx.x * 256 + threadIdx.x;  // float4 index, half 0
        size_t i1 = i0 + XCH;                                // half 1
        float4 v0 = reinterpret_cast<const float4*>(X)[i0];
        float4 v1 = reinterpret_cast<const float4*>(X)[i1];
        uint2 h0, h1;
        h0.x = pack_h2(v0.x, v0.y); h0.y = pack_h2(v0.z, v0.w);
        h1.x = pack_h2(v1.x, v1.y); h1.y = pack_h2(v1.z, v1.w);
        reinterpret_cast<uint2*>(g_Xh)[i0] = h0;
        reinterpret_cast<uint2*>(g_Xh)[i1] = h1;
        if (i0 < (size_t)(B_SZ * E_SZ) / 4)
            reinterpret_cast<float4*>(g_S)[i0] = make_float4(0.f, 0.f, 0.f, 0.f);
        return;
    }
    // W transpose path: tile 32 u-cols x 64 d-rows; t[u][d], d padded to 65
    __shared__ float t[32][65];
    const int bid = blockIdx.x - XBLK;
    const int nu  = U_SZ / 32;                    // 32
    const int nd  = D_K / 64;                     // 16
    const int u0  = (bid % nu) * 32;
    const int d0  = ((bid / nu) % nd) * 64;
    const int e   = bid / (nu * nd);
    const int tx  = threadIdx.x & 31;
    const int ty  = threadIdx.x >> 5;             // 0..7
#pragma unroll
    for (int i = 0; i < 8; i++) {
        int dl = ty + i * 8;
        t[tx][dl] = W[((size_t)e * D_K + d0 + dl) * U_SZ + u0 + tx];
    }
    __syncthreads();
#pragma unroll
    for (int i = 0; i < 4; i++) {
        int ul = ty + i * 8;
        float lo = t[ul][tx * 2];
        float hi = t[ul][tx * 2 + 1];
        *reinterpret_cast<uint32_t*>(
            &g_Wth[((size_t)e * U_SZ + u0 + ul) * D_K + d0 + tx * 2]) = pack_h2(lo, hi);
    }
}

// ----------------------------------------------------------------------------
// Kernel 2: batched GEMM (fp16 HMMA k16, 2 CTAs/SM) + exp + row-sum
// grid: (U/TN = 8, B/TM = 64, E = 16), 256 threads
__global__ void __launch_bounds__(ATHREADS, 2)
gemm_exp_kernel(const float* __restrict__ bias) {
    extern __shared__ char smem[];
    const uint32_t sb = smem_u32(smem);
    const int tid  = threadIdx.x;
    const int lane = tid & 31;
    const int wid  = tid >> 5;
    const int warp_m = wid & 3;        // 0..3  (32-row slab)
    const int warp_n = wid >> 2;       // 0..1  (64-col slab)
    const int g  = lane >> 2;          // 0..7
    const int t4 = lane & 3;           // 0..3
    const int n0 = blockIdx.x * TN;
    const int b0 = blockIdx.y * TM;
    const int e  = blockIdx.z;

    float* biasS = reinterpret_cast<float*>(smem + SM_BIAS);
    float* srowS = reinterpret_cast<float*>(smem + SM_SROW);
    if (tid < TN) biasS[tid] = bias[(size_t)e * U_SZ + n0 + tid];
    if (tid >= 128 && tid < 128 + TM) srowS[tid - 128] = 0.0f;

    const __half* gA = g_Xh + (size_t)b0 * D_K;
    const __half* gB = g_Wth + ((size_t)e * U_SZ + n0) * D_K;

    auto load_tile = [&](int kt, int stage) {
        const int k0 = kt * KC;
        const uint32_t base = sb + SM_STAGE + stage * STAGE_BYTES;
#pragma unroll
        for (int t = 0; t < 4; t++) {            // A: 1024 16B granules
            int uid = tid + t * ATHREADS;
            int row = uid >> 3, gr = uid & 7;
            cp16(base + swz128((uint32_t)(row * 128 + gr * 16)),
                 gA + (size_t)row * D_K + k0 + gr * 8);
        }
#pragma unroll
        for (int t = 0; t < 4; t++) {            // B: 1024 granules
            int uid = tid + t * ATHREADS;
            int row = uid >> 3, gr = uid & 7;
            cp16(base + A_BYTES + swz128((uint32_t)(row * 128 + gr * 16)),
                 gB + (size_t)row * D_K + k0 + gr * 8);
        }
        cp_commit();
    };

    float acc[2][8][4];                          // warp tile 32x64
#pragma unroll
    for (int mi = 0; mi < 2; mi++)
#pragma unroll
        for (int nf = 0; nf < 8; nf++)
#pragma unroll
            for (int q = 0; q < 4; q++) acc[mi][nf][q] = 0.0f;

    load_tile(0, 0);
    load_tile(1, 1);
    for (int kt = 0; kt < NKT; kt++) {
        if (kt < NKT - 1) cp_wait<1>();
        else              cp_wait<0>();
        __syncthreads();
        if (kt + 2 < NKT) load_tile(kt + 2, (kt + 2) % NSTAGE);

        const uint32_t aBase = sb + SM_STAGE + (kt % NSTAGE) * STAGE_BYTES;
        const uint32_t bBase = aBase + A_BYTES;
#pragma unroll
        for (int s = 0; s < 4; s++) {
            const uint32_t colb = (uint32_t)(s * 32 + (lane >> 4) * 16);
            uint32_t a[2][4], b[4][4];
#pragma unroll
            for (int mi = 0; mi < 2; mi++) {
                uint32_t off = swz128((uint32_t)((warp_m * 32 + mi * 16 + (lane & 15)) * 128) + colb);
                ldsm4(a[mi], aBase + off);
            }
#pragma unroll
            for (int nj = 0; nj < 4; nj++) {
                uint32_t off = swz128((uint32_t)((warp_n * 64 + nj * 16 + (lane & 15)) * 128) + colb);
                ldsm4(b[nj], bBase + off);
            }
#pragma unroll
            for (int mi = 0; mi < 2; mi++) {
#pragma unroll
                for (int nf = 0; nf < 8; nf++) {
                    const int nj = nf >> 1, p = nf & 1;
                    mma_f16(acc[mi][nf], a[mi], b[nj][p], b[nj][p + 2]);
                }
            }
        }
    }

    // ---- Epilogue: +bias, exp, row sums; SMEM-repacked coalesced P stores ----
    __half* Pg = g_P;
    uint32_t pbuf = sb + SM_PACK;
#pragma unroll
    for (int mi = 0; mi < 2; mi++) {
#pragma unroll
        for (int h = 0; h < 2; h++) {
            float s_lo = 0.0f, s_hi = 0.0f;
            const int lr_lo = warp_m * 16 + g;       // local pack row (0..63)
            const int lr_hi = lr_lo + 8;
#pragma unroll
            for (int nfl = 0; nfl < 4; nfl++) {
                const int nf = h * 4 + nfl;
                const int colg = warp_n * 64 + nf * 8 + t4 * 2;      // global tile col
                const float bz0 = biasS[colg], bz1 = biasS[colg + 1];
                float e00 = __expf(acc[mi][nf][0] + bz0);
                float e01 = __expf(acc[mi][nf][1] + bz1);
                float e10 = __expf(acc[mi][nf][2] + bz0);
                float e11 = __expf(acc[mi][nf][3] + bz1);
                s_lo += e00 + e01;
                s_hi += e10 + e11;
                const uint32_t cb = (uint32_t)(warp_n * 64 + nfl * 16 + t4 * 4); // byte col in pack row
                asm volatile("st.shared.b32 [%0], %1;" ::
                             "r"(pbuf + (uint32_t)lr_lo * PACK_STRIDE + cb), "r"(pack_h2(e00, e01)) : "memory");
                asm volatile("st.shared.b32 [%0], %1;" ::
                             "r"(pbuf + (uint32_t)lr_hi * PACK_STRIDE + cb), "r"(pack_h2(e10, e11)) : "memory");
            }
            s_lo += __shfl_xor_sync(0xFFFFFFFFu, s_lo, 1);
            s_lo += __shfl_xor_sync(0xFFFFFFFFu, s_lo, 2);
            s_hi += __shfl_xor_sync(0xFFFFFFFFu, s_hi, 1);
            s_hi += __shfl_xor_sync(0xFFFFFFFFu, s_hi, 2);
            if (t4 == 0) {
                atomicAdd(&srowS[warp_m * 32 + mi * 16 + g], s_lo);
                atomicAdd(&srowS[warp_m * 32 + mi * 16 + g + 8], s_hi);
            }
            __syncthreads();
            // coalesced copy-out: 64 rows x 128B (streaming stores)
#pragma unroll
            for (int it = 0; it < 2; it++) {
                const int s_ = tid + it * 256;
                const int row = s_ >> 3, k = s_ & 7;
                uint4 v;
                asm volatile("ld.shared.v4.u32 {%0,%1,%2,%3}, [%4];"
                             : "=r"(v.x), "=r"(v.y), "=r"(v.z), "=r"(v.w)
                             : "r"(pbuf + (uint32_t)row * PACK_STRIDE + (uint32_t)k * 16));
                const int grow = (row >> 4) * 32 + mi * 16 + (row & 15);
                const int gcol = (k >> 2) * 64 + h * 32 + (k & 3) * 8;
                stg_cs_v4(Pg + ((size_t)(b0 + grow) * E_SZ + e) * U_SZ + n0 + gcol, v);
            }
            __syncthreads();
        }
    }
    if (tid < TM) atomicAdd(&g_S[(size_t)(b0 + tid) * E_SZ + e], srowS[tid]);
}

// ----------------------------------------------------------------------------
// Kernel 3: out[b][u] = sum_e tp[b][e]/S[b][e] * P[b][e][u]
// 128 threads; loads batched in groups of 4 e's for MLP=4.
__global__ void __launch_bounds__(128)
combine_kernel(const float* __restrict__ tp, float* __restrict__ out) {
    const int b = blockIdx.x;
    __shared__ float c[E_SZ];
    if (threadIdx.x < E_SZ)
        c[threadIdx.x] = tp[(size_t)b * E_SZ + threadIdx.x]
                       / g_S[(size_t)b * E_SZ + threadIdx.x];
    __syncthreads();
    const int u0 = threadIdx.x * 8;
    float a[8];
#pragma unroll
    for (int j = 0; j < 8; j++) a[j] = 0.0f;
    const __half* Pb = g_P + (size_t)b * E_SZ * U_SZ;
#pragma unroll
    for (int eg = 0; eg < E_SZ; eg += 4) {
        uint4 q[4];
#pragma unroll
        for (int j = 0; j < 4; j++)
            q[j] = ldg_cs_v4(Pb + (size_t)(eg + j) * U_SZ + u0);
#pragma unroll
        for (int j = 0; j < 4; j++) {
            const float ce = c[eg + j];
            float2 f0 = __half22float2(*reinterpret_cast<const __half2*>(&q[j].x));
            float2 f1 = __half22float2(*reinterpret_cast<const __half2*>(&q[j].y));
            float2 f2 = __half22float2(*reinterpret_cast<const __half2*>(&q[j].z));
            float2 f3 = __half22float2(*reinterpret_cast<const __half2*>(&q[j].w));
            a[0] += ce * f0.x; a[1] += ce * f0.y;
            a[2] += ce * f1.x; a[3] += ce * f1.y;
            a[4] += ce * f2.x; a[5] += ce * f2.y;
            a[6] += ce * f3.x; a[7] += ce * f3.y;
        }
    }
    float* ob = out + (size_t)b * U_SZ + u0;
    uint4 o0, o1;
    o0.x = __float_as_uint(a[0]); o0.y = __float_as_uint(a[1]);
    o0.z = __float_as_uint(a[2]); o0.w = __float_as_uint(a[3]);
    o1.x = __float_as_uint(a[4]); o1.y = __float_as_uint(a[5]);
    o1.z = __float_as_uint(a[6]); o1.w = __float_as_uint(a[7]);
    stg_cs_v4(ob, o0);
    stg_cs_v4(ob + 4, o1);
}

// ----------------------------------------------------------------------------
extern "C" void kernel_launch(void* const* d_in, const int* in_sizes, int n_in,
                              void* d_out, int out_size) {
    (void)in_sizes; (void)n_in; (void)out_size;
    const float* X    = (const float*)d_in[0];  // [B, D]
    const float* tp   = (const float*)d_in[1];  // [B, E, 1]
    const float* W    = (const float*)d_in[2];  // [E, D, U]
    const float* bias = (const float*)d_in[3];  // [E, U]
    float* out = (float*)d_out;

    cudaFuncSetAttribute(gemm_exp_kernel,
                         cudaFuncAttributeMaxDynamicSharedMemorySize, SMEM_TOTAL);

    prep_kernel<<<XBLK + WBLK, 256>>>(X, W);
    gemm_exp_kernel<<<dim3(U_SZ / TN, B_SZ / TM, E_SZ), ATHREADS, SMEM_TOTAL>>>(bias);
    combine_kernel<<<B_SZ, 128>>>(tp, out);
}

// round 17
// speedup vs baseline: 1.0003x; 1.0003x over previous
#include <cuda_runtime.h>
#include <cuda_fp16.h>
#include <cstdint>

// ----------------------------------------------------------------------------
// Problem constants
#define B_SZ  8192
#define D_K   1024
#define U_SZ  1024
#define E_SZ  16

// GEMM tile config: 128x128 CTA tile, 8 warps (32x64 warp tiles), 2 CTAs/SM
constexpr int TM = 128;
constexpr int TN = 128;
constexpr int KC = 64;                // K per SMEM stage (fp16: 128B rows)
constexpr int NKT = D_K / KC;         // 16
constexpr int NSTAGE = 3;
constexpr int ATHREADS = 256;         // 8 warps, warp tile 32x64

// ----------------------------------------------------------------------------
// Static device scratch (allocation-free rule)
__device__ __half g_Xh[(size_t)B_SZ * D_K];                    // fp16 X
__device__ __half g_Wth[(size_t)E_SZ * U_SZ * D_K];            // fp16 W^T [e][u][d]
__device__ __half g_P[(size_t)B_SZ * E_SZ * U_SZ];             // exp(logits), b-major [b][e][u]
__device__ float  g_S[(size_t)B_SZ * E_SZ];                    // row sums Z, [b][e]

// ----------------------------------------------------------------------------
__device__ __forceinline__ uint32_t smem_u32(const void* p) {
    return (uint32_t)__cvta_generic_to_shared(p);
}
__device__ __forceinline__ void cp16(uint32_t dst, const void* src) {
    asm volatile("cp.async.cg.shared.global [%0], [%1], 16;" :: "r"(dst), "l"(src));
}
__device__ __forceinline__ void cp_commit() {
    asm volatile("cp.async.commit_group;" ::: "memory");
}
template <int N> __device__ __forceinline__ void cp_wait() {
    asm volatile("cp.async.wait_group %0;" :: "n"(N) : "memory");
}
__device__ __forceinline__ void ldsm4(uint32_t* r, uint32_t addr) {
    asm volatile("ldmatrix.sync.aligned.m8n8.x4.shared.b16 {%0,%1,%2,%3}, [%4];"
                 : "=r"(r[0]), "=r"(r[1]), "=r"(r[2]), "=r"(r[3]) : "r"(addr));
}
__device__ __forceinline__ void mma_f16(float* c, const uint32_t* a, uint32_t b0, uint32_t b1) {
    asm volatile("mma.sync.aligned.m16n8k16.row.col.f32.f16.f16.f32 "
                 "{%0,%1,%2,%3}, {%4,%5,%6,%7}, {%8,%9}, {%0,%1,%2,%3};"
                 : "+f"(c[0]), "+f"(c[1]), "+f"(c[2]), "+f"(c[3])
                 : "r"(a[0]), "r"(a[1]), "r"(a[2]), "r"(a[3]), "r"(b0), "r"(b1));
}
__device__ __forceinline__ uint32_t swz128(uint32_t off) { return off ^ ((off >> 3) & 0x70); }
__device__ __forceinline__ uint32_t pack_h2(float a, float b) {
    __half2 h = __floats2half2_rn(a, b);
    return *reinterpret_cast<uint32_t*>(&h);
}
// streaming (evict-first) global accesses for single-use data
__device__ __forceinline__ uint4 ldg_cs_v4(const void* p) {
    uint4 v;
    asm volatile("ld.global.cs.v4.u32 {%0,%1,%2,%3}, [%4];"
                 : "=r"(v.x), "=r"(v.y), "=r"(v.z), "=r"(v.w) : "l"(p));
    return v;
}
__device__ __forceinline__ void stg_cs_v4(void* p, uint4 v) {
    asm volatile("st.global.cs.v4.u32 [%0], {%1,%2,%3,%4};"
                 :: "l"(p), "r"(v.x), "r"(v.y), "r"(v.z), "r"(v.w) : "memory");
}

// ----------------------------------------------------------------------------
// SMEM layout (bytes)
constexpr int SM_BIAS  = 0;                      // 128 floats
constexpr int SM_SROW  = 512;                    // 128 floats
constexpr int SM_STAGE = 1024;                   // 1024-aligned
constexpr int A_BYTES  = TM * 128;               // 16KB
constexpr int B_BYTES  = TN * 128;               // 16KB
constexpr int STAGE_BYTES = A_BYTES + B_BYTES;   // 32KB
constexpr int SM_PACK  = SM_STAGE + NSTAGE * STAGE_BYTES;     // 99328
constexpr int PACK_STRIDE = 144;                 // 16B-aligned, 36-bank stride (conflict-free)
constexpr int PACK_BYTES  = 64 * PACK_STRIDE;    // 9216
constexpr int SMEM_TOTAL  = SM_PACK + PACK_BYTES;             // 108544 -> 2 CTAs/SM

// ----------------------------------------------------------------------------
// Kernel 1 (merged prep): convert X to fp16, zero S, transpose+convert W.
// W path: 32u x 64d tiles, t[u][d] layout -> conflict-free LDS both phases.
constexpr int XBLK = (B_SZ * D_K / 4) / 256;                         // 8192
constexpr int WBLK = (U_SZ / 32) * (D_K / 64) * E_SZ;                // 8192

__global__ void prep_kernel(const float* __restrict__ X, const float* __restrict__ W) {
    if (blockIdx.x < XBLK) {
        size_t i = (size_t)blockIdx.x * 256 + threadIdx.x;   // float4 index
        float4 v = reinterpret_cast<const float4*>(X)[i];
        uint2 h;
        h.x = pack_h2(v.x, v.y);
        h.y = pack_h2(v.z, v.w);
        reinterpret_cast<uint2*>(g_Xh)[i] = h;
        if (i < (size_t)(B_SZ * E_SZ) / 4)
            reinterpret_cast<float4*>(g_S)[i] = make_float4(0.f, 0.f, 0.f, 0.f);
        return;
    }
    // W transpose path: tile 32 u-cols x 64 d-rows; t[u][d], d padded to 65
    __shared__ float t[32][65];
    const int bid = blockIdx.x - XBLK;
    const int nu  = U_SZ / 32;                    // 32
    const int nd  = D_K / 64;                     // 16
    const int u0  = (bid % nu) * 32;
    const int d0  = ((bid / nu) % nd) * 64;
    const int e   = bid / (nu * nd);
    const int tx  = threadIdx.x & 31;
    const int ty  = threadIdx.x >> 5;             // 0..7
#pragma unroll
    for (int i = 0; i < 8; i++) {
        int dl = ty + i * 8;
        t[tx][dl] = W[((size_t)e * D_K + d0 + dl) * U_SZ + u0 + tx];
    }
    __syncthreads();
#pragma unroll
    for (int i = 0; i < 4; i++) {
        int ul = ty + i * 8;
        float lo = t[ul][tx * 2];
        float hi = t[ul][tx * 2 + 1];
        *reinterpret_cast<uint32_t*>(
            &g_Wth[((size_t)e * U_SZ + u0 + ul) * D_K + d0 + tx * 2]) = pack_h2(lo, hi);
    }
}

// ----------------------------------------------------------------------------
// Kernel 2: batched GEMM (fp16 HMMA k16, 2 CTAs/SM) + exp + row-sum
// grid: (U/TN = 8, B/TM = 64, E = 16), 256 threads
__global__ void __launch_bounds__(ATHREADS, 2)
gemm_exp_kernel(const float* __restrict__ bias) {
    extern __shared__ char smem[];
    const uint32_t sb = smem_u32(smem);
    const int tid  = threadIdx.x;
    const int lane = tid & 31;
    const int wid  = tid >> 5;
    const int warp_m = wid & 3;        // 0..3  (32-row slab)
    const int warp_n = wid >> 2;       // 0..1  (64-col slab)
    const int g  = lane >> 2;          // 0..7
    const int t4 = lane & 3;           // 0..3
    const int n0 = blockIdx.x * TN;
    const int b0 = blockIdx.y * TM;
    const int e  = blockIdx.z;

    float* biasS = reinterpret_cast<float*>(smem + SM_BIAS);
    float* srowS = reinterpret_cast<float*>(smem + SM_SROW);
    if (tid < TN) biasS[tid] = bias[(size_t)e * U_SZ + n0 + tid];
    if (tid >= 128 && tid < 128 + TM) srowS[tid - 128] = 0.0f;

    const __half* gA = g_Xh + (size_t)b0 * D_K;
    const __half* gB = g_Wth + ((size_t)e * U_SZ + n0) * D_K;

    auto load_tile = [&](int kt, int stage) {
        const int k0 = kt * KC;
        const uint32_t base = sb + SM_STAGE + stage * STAGE_BYTES;
#pragma unroll
        for (int t = 0; t < 4; t++) {            // A: 1024 16B granules
            int uid = tid + t * ATHREADS;
            int row = uid >> 3, gr = uid & 7;
            cp16(base + swz128((uint32_t)(row * 128 + gr * 16)),
                 gA + (size_t)row * D_K + k0 + gr * 8);
        }
#pragma unroll
        for (int t = 0; t < 4; t++) {            // B: 1024 granules
            int uid = tid + t * ATHREADS;
            int row = uid >> 3, gr = uid & 7;
            cp16(base + A_BYTES + swz128((uint32_t)(row * 128 + gr * 16)),
                 gB + (size_t)row * D_K + k0 + gr * 8);
        }
        cp_commit();
    };

    float acc[2][8][4];                          // warp tile 32x64
#pragma unroll
    for (int mi = 0; mi < 2; mi++)
#pragma unroll
        for (int nf = 0; nf < 8; nf++)
#pragma unroll
            for (int q = 0; q < 4; q++) acc[mi][nf][q] = 0.0f;

    load_tile(0, 0);
    load_tile(1, 1);
    for (int kt = 0; kt < NKT; kt++) {
        if (kt < NKT - 1) cp_wait<1>();
        else              cp_wait<0>();
        __syncthreads();
        if (kt + 2 < NKT) load_tile(kt + 2, (kt + 2) % NSTAGE);

        const uint32_t aBase = sb + SM_STAGE + (kt % NSTAGE) * STAGE_BYTES;
        const uint32_t bBase = aBase + A_BYTES;
#pragma unroll
        for (int s = 0; s < 4; s++) {
            const uint32_t colb = (uint32_t)(s * 32 + (lane >> 4) * 16);
            uint32_t a[2][4], b[4][4];
#pragma unroll
            for (int mi = 0; mi < 2; mi++) {
                uint32_t off = swz128((uint32_t)((warp_m * 32 + mi * 16 + (lane & 15)) * 128) + colb);
                ldsm4(a[mi], aBase + off);
            }
#pragma unroll
            for (int nj = 0; nj < 4; nj++) {
                uint32_t off = swz128((uint32_t)((warp_n * 64 + nj * 16 + (lane & 15)) * 128) + colb);
                ldsm4(b[nj], bBase + off);
            }
#pragma unroll
            for (int mi = 0; mi < 2; mi++) {
#pragma unroll
                for (int nf = 0; nf < 8; nf++) {
                    const int nj = nf >> 1, p = nf & 1;
                    mma_f16(acc[mi][nf], a[mi], b[nj][p], b[nj][p + 2]);
                }
            }
        }
    }

    // ---- Epilogue: +bias, exp, row sums; SMEM-repacked coalesced P stores ----
    __half* Pg = g_P;
    uint32_t pbuf = sb + SM_PACK;
#pragma unroll
    for (int mi = 0; mi < 2; mi++) {
#pragma unroll
        for (int h = 0; h < 2; h++) {
            float s_lo = 0.0f, s_hi = 0.0f;
            const int lr_lo = warp_m * 16 + g;       // local pack row (0..63)
            const int lr_hi = lr_lo + 8;
#pragma unroll
            for (int nfl = 0; nfl < 4; nfl++) {
                const int nf = h * 4 + nfl;
                const int colg = warp_n * 64 + nf * 8 + t4 * 2;      // global tile col
                const float bz0 = biasS[colg], bz1 = biasS[colg + 1];
                float e00 = __expf(acc[mi][nf][0] + bz0);
                float e01 = __expf(acc[mi][nf][1] + bz1);
                float e10 = __expf(acc[mi][nf][2] + bz0);
                float e11 = __expf(acc[mi][nf][3] + bz1);
                s_lo += e00 + e01;
                s_hi += e10 + e11;
                const uint32_t cb = (uint32_t)(warp_n * 64 + nfl * 16 + t4 * 4); // byte col in pack row
                asm volatile("st.shared.b32 [%0], %1;" ::
                             "r"(pbuf + (uint32_t)lr_lo * PACK_STRIDE + cb), "r"(pack_h2(e00, e01)) : "memory");
                asm volatile("st.shared.b32 [%0], %1;" ::
                             "r"(pbuf + (uint32_t)lr_hi * PACK_STRIDE + cb), "r"(pack_h2(e10, e11)) : "memory");
            }
            s_lo += __shfl_xor_sync(0xFFFFFFFFu, s_lo, 1);
            s_lo += __shfl_xor_sync(0xFFFFFFFFu, s_lo, 2);
            s_hi += __shfl_xor_sync(0xFFFFFFFFu, s_hi, 1);
            s_hi += __shfl_xor_sync(0xFFFFFFFFu, s_hi, 2);
            if (t4 == 0) {
                atomicAdd(&srowS[warp_m * 32 + mi * 16 + g], s_lo);
                atomicAdd(&srowS[warp_m * 32 + mi * 16 + g + 8], s_hi);
            }
            __syncthreads();
            // coalesced copy-out: 64 rows x 128B (streaming stores)
#pragma unroll
            for (int it = 0; it < 2; it++) {
                const int s_ = tid + it * 256;
                const int row = s_ >> 3, k = s_ & 7;
                uint4 v;
                asm volatile("ld.shared.v4.u32 {%0,%1,%2,%3}, [%4];"
                             : "=r"(v.x), "=r"(v.y), "=r"(v.z), "=r"(v.w)
                             : "r"(pbuf + (uint32_t)row * PACK_STRIDE + (uint32_t)k * 16));
                const int grow = (row >> 4) * 32 + mi * 16 + (row & 15);
                const int gcol = (k >> 2) * 64 + h * 32 + (k & 3) * 8;
                stg_cs_v4(Pg + ((size_t)(b0 + grow) * E_SZ + e) * U_SZ + n0 + gcol, v);
            }
            __syncthreads();
        }
    }
    if (tid < TM) atomicAdd(&g_S[(size_t)(b0 + tid) * E_SZ + e], srowS[tid]);
}

// ----------------------------------------------------------------------------
// Kernel 3: out[b][u] = sum_e tp[b][e]/S[b][e] * P[b][e][u]
// 128 threads; streaming loads (P read exactly once).
__global__ void combine_kernel(const float* __restrict__ tp, float* __restrict__ out) {
    const int b = blockIdx.x;
    __shared__ float c[E_SZ];
    if (threadIdx.x < E_SZ)
        c[threadIdx.x] = tp[(size_t)b * E_SZ + threadIdx.x]
                       / g_S[(size_t)b * E_SZ + threadIdx.x];
    __syncthreads();
    const int u0 = threadIdx.x * 8;
    float a[8];
#pragma unroll
    for (int j = 0; j < 8; j++) a[j] = 0.0f;
    const __half* Pb = g_P + (size_t)b * E_SZ * U_SZ;
#pragma unroll
    for (int e = 0; e < E_SZ; e++) {
        const uint4 q = ldg_cs_v4(Pb + (size_t)e * U_SZ + u0);
        const float ce = c[e];
        float2 f0 = __half22float2(*reinterpret_cast<const __half2*>(&q.x));
        float2 f1 = __half22float2(*reinterpret_cast<const __half2*>(&q.y));
        float2 f2 = __half22float2(*reinterpret_cast<const __half2*>(&q.z));
        float2 f3 = __half22float2(*reinterpret_cast<const __half2*>(&q.w));
        a[0] += ce * f0.x; a[1] += ce * f0.y;
        a[2] += ce * f1.x; a[3] += ce * f1.y;
        a[4] += ce * f2.x; a[5] += ce * f2.y;
        a[6] += ce * f3.x; a[7] += ce * f3.y;
    }
    float* ob = out + (size_t)b * U_SZ + u0;
    uint4 o0, o1;
    o0.x = __float_as_uint(a[0]); o0.y = __float_as_uint(a[1]);
    o0.z = __float_as_uint(a[2]); o0.w = __float_as_uint(a[3]);
    o1.x = __float_as_uint(a[4]); o1.y = __float_as_uint(a[5]);
    o1.z = __float_as_uint(a[6]); o1.w = __float_as_uint(a[7]);
    stg_cs_v4(ob, o0);
    stg_cs_v4(ob + 4, o1);
}

// ----------------------------------------------------------------------------
extern "C" void kernel_launch(void* const* d_in, const int* in_sizes, int n_in,
                              void* d_out, int out_size) {
    (void)in_sizes; (void)n_in; (void)out_size;
    const float* X    = (const float*)d_in[0];  // [B, D]
    const float* tp   = (const float*)d_in[1];  // [B, E, 1]
    const float* W    = (const float*)d_in[2];  // [E, D, U]
    const float* bias = (const float*)d_in[3];  // [E, U]
    float* out = (float*)d_out;

    cudaFuncSetAttribute(gemm_exp_kernel,
                         cudaFuncAttributeMaxDynamicSharedMemorySize, SMEM_TOTAL);

    prep_kernel<<<XBLK + WBLK, 256>>>(X, W);
    gemm_exp_kernel<<<dim3(U_SZ / TN, B_SZ / TM, E_SZ), ATHREADS, SMEM_TOTAL>>>(bias);
    combine_kernel<<<B_SZ, 128>>>(tp, out);
}